// round 14
// baseline (speedup 1.0000x reference)
#include <cuda_runtime.h>
#include <cuda_fp16.h>
#include <math.h>
#include <stdint.h>

#define NB   4
#define LQ   2048
#define LK   2048
#define DIM  1024
#define NH   16
#define DH   64

// ---------------- scratch (static device arrays; no allocation) -------------
__device__ __half g_Xqh[NB * LQ * DIM];
__device__ __half g_Xkh[NB * LK * DIM];
__device__ __half g_Xkl[NB * LK * DIM];
__device__ __half g_Wh[3 * DIM * DIM];
__device__ __half g_Qh[NB * NH * LQ * DH];
__device__ __half g_Kh[NB * NH * LK * DH];   // pre-scaled by rscale[n]*log2(e)
__device__ __half g_Vh[NB * NH * LK * DH];
__device__ int   g_valid[NB];
__device__ float g_rscale[NB];

// ========================= low-level helpers ================================
__device__ __forceinline__ uint32_t smem_u32(const void* p) {
    uint32_t a;
    asm("{ .reg .u64 t; cvta.to.shared.u64 t, %1; cvt.u32.u64 %0, t; }"
        : "=r"(a) : "l"(p));
    return a;
}

__device__ __forceinline__ float ex2(float x) {
    float r;
    asm("ex2.approx.f32 %0, %1;" : "=f"(r) : "f"(x));
    return r;
}

__device__ __forceinline__ void cpa16(uint32_t dst, const void* src) {
    asm volatile("cp.async.cg.shared.global [%0], [%1], 16;"
                 :: "r"(dst), "l"(src) : "memory");
}
#define CP_COMMIT() asm volatile("cp.async.commit_group;" ::: "memory")
#define CP_WAIT1()  asm volatile("cp.async.wait_group 1;" ::: "memory")

__device__ __forceinline__ void ldsm4(uint32_t* r, uint32_t addr) {
    asm volatile("ldmatrix.sync.aligned.m8n8.x4.shared.b16 {%0,%1,%2,%3}, [%4];"
                 : "=r"(r[0]), "=r"(r[1]), "=r"(r[2]), "=r"(r[3]) : "r"(addr));
}
__device__ __forceinline__ void ldsm4t(uint32_t* r, uint32_t addr) {
    asm volatile("ldmatrix.sync.aligned.m8n8.x4.trans.shared.b16 {%0,%1,%2,%3}, [%4];"
                 : "=r"(r[0]), "=r"(r[1]), "=r"(r[2]), "=r"(r[3]) : "r"(addr));
}

__device__ __forceinline__ void mma16816(float* d, const uint32_t* a,
                                         const uint32_t* b) {
    asm volatile(
        "mma.sync.aligned.m16n8k16.row.col.f32.f16.f16.f32 "
        "{%0,%1,%2,%3}, {%4,%5,%6,%7}, {%8,%9}, {%0,%1,%2,%3};"
        : "+f"(d[0]), "+f"(d[1]), "+f"(d[2]), "+f"(d[3])
        : "r"(a[0]), "r"(a[1]), "r"(a[2]), "r"(a[3]), "r"(b[0]), "r"(b[1]));
}

__device__ __forceinline__ void hilo_h2(float a, float b, uint32_t& h, uint32_t& l) {
    __half ha = __float2half_rn(a);
    __half hb = __float2half_rn(b);
    float ra = a - __half2float(ha);
    float rb = b - __half2float(hb);
    __half2 H = __halves2half2(ha, hb);
    __half2 L = __floats2half2_rn(ra, rb);
    h = *reinterpret_cast<uint32_t*>(&H);
    l = *reinterpret_cast<uint32_t*>(&L);
}

__device__ __forceinline__ uint32_t h2_only(float a, float b) {
    __half2 H = __floats2half2_rn(a, b);
    return *reinterpret_cast<uint32_t*>(&H);
}

// ============ fused prep: valid-count + all f32->fp16 conversions ============
// Region map (256-thread blocks):
//   [0, 4096)        : query -> g_Xqh (hi only)             8M elems
//   [4096, 8192)     : key   -> g_Xkh + g_Xkl (hi/lo)       8M elems
//   [8192, 9728)     : W q/k/v -> g_Wh (hi only)            3x1M elems
//   [9728, 9732)     : valid count (4 blocks)
#define PREP_BLOCKS 9732

__global__ void prep_kernel(const float* __restrict__ query,
                            const float* __restrict__ key,
                            const float* __restrict__ Wq,
                            const float* __restrict__ Wk,
                            const float* __restrict__ Wv,
                            const void*  __restrict__ pad) {
    const int b = blockIdx.x;
    const int tid = threadIdx.x;

    if (b < 4096) {                        // query hi
        int i = (b * 256 + tid) * 8;
        float4 a = *reinterpret_cast<const float4*>(query + i);
        float4 c = *reinterpret_cast<const float4*>(query + i + 4);
        uint4 H;
        H.x = h2_only(a.x, a.y); H.y = h2_only(a.z, a.w);
        H.z = h2_only(c.x, c.y); H.w = h2_only(c.z, c.w);
        *reinterpret_cast<uint4*>(g_Xqh + i) = H;
        return;
    }
    if (b < 8192) {                        // key hi/lo
        int i = ((b - 4096) * 256 + tid) * 8;
        float4 a = *reinterpret_cast<const float4*>(key + i);
        float4 c = *reinterpret_cast<const float4*>(key + i + 4);
        uint4 H, L;
        hilo_h2(a.x, a.y, H.x, L.x);
        hilo_h2(a.z, a.w, H.y, L.y);
        hilo_h2(c.x, c.y, H.z, L.z);
        hilo_h2(c.z, c.w, H.w, L.w);
        *reinterpret_cast<uint4*>(g_Xkh + i) = H;
        *reinterpret_cast<uint4*>(g_Xkl + i) = L;
        return;
    }
    if (b < 9728) {                        // weights hi
        int wi = (b - 8192) / 512;         // 0:Wq 1:Wk 2:Wv
        const float* W = (wi == 0) ? Wq : (wi == 1) ? Wk : Wv;
        int i = (((b - 8192) & 511) * 256 + tid) * 8;
        float4 a = *reinterpret_cast<const float4*>(W + i);
        float4 c = *reinterpret_cast<const float4*>(W + i + 4);
        uint4 H;
        H.x = h2_only(a.x, a.y); H.y = h2_only(a.z, a.w);
        H.z = h2_only(c.x, c.y); H.w = h2_only(c.z, c.w);
        *reinterpret_cast<uint4*>(g_Wh + (size_t)wi * DIM * DIM + i) = H;
        return;
    }

    // ---- valid count (4 blocks; result consumed only by later kernels) ----
    const int n = b - 9728;
    __shared__ int red[256];

    const unsigned* w = (const unsigned*)pad;
    int f = 0;
    for (int i = tid; i < 2048; i += 256) {
        unsigned v = w[i];
        if (v == 0x3F800000u) f |= 4;
        else if (v == 0x00000001u) f |= 2;
        else if (v == 0x01000000u || v == 0x01010000u ||
                 v == 0x01010100u || v == 0x01010101u) f |= 1;
    }
    red[tid] = f;
    __syncthreads();
    for (int s = 128; s > 0; s >>= 1) {
        if (tid < s) red[tid] |= red[tid + s];
        __syncthreads();
    }
    const int fl = red[0];
    const int layout = (fl & 1) ? 0 : ((fl & 4) ? 2 : 1);
    __syncthreads();

    int c = 0;
    if (layout == 0) {
        const unsigned char* p = (const unsigned char*)pad;
        for (int j = tid; j < LK; j += 256) c += (p[n * LK + j] == 0);
    } else if (layout == 1) {
        const int* p = (const int*)pad;
        for (int j = tid; j < LK; j += 256) c += (p[n * LK + j] == 0);
    } else {
        const float* p = (const float*)pad;
        for (int j = tid; j < LK; j += 256) c += (p[n * LK + j] == 0.0f);
    }
    red[tid] = c;
    __syncthreads();
    for (int s = 128; s > 0; s >>= 1) {
        if (tid < s) red[tid] += red[tid + s];
        __syncthreads();
    }
    if (tid == 0) {
        g_valid[n]  = red[0];
        g_rscale[n] = rsqrtf((float)red[0]);
    }
}

// ======================= merged projection kernel ============================
// z=0: Q = Xq @ Wq^T (1-pass).  z=1: K = Xk @ Wk^T (1-pass, *rscale*log2e).
// z=2: V = Xk @ Wv^T (2-pass: AhBh + AlBh).
// Stage: 3 matrix slots (Ah, Al, Bh); z=0/1 skip Al. Occupancy 2.
#define PSTR    40
#define PROWB   (PSTR * 2)               // 80 bytes
#define PMATB   (128 * PROWB)            // 10240 bytes per matrix tile
#define P_STGB  (3 * PMATB)              // 30720 per stage
#define P_SMEM  (2 * P_STGB)             // 61440

__global__ __launch_bounds__(256, 2)
void proj_kernel(int dummy) {
    extern __shared__ char smem[];
    const uint32_t sb = smem_u32(smem);

    const int tid  = threadIdx.x;
    const int wid  = tid >> 5;
    const int lane = tid & 31;
    const int grp  = lane >> 3;

    const int which = blockIdx.z;
    const bool two_pass = (which == 2);
    const __half* __restrict__ XH = (which == 0) ? g_Xqh : g_Xkh;
    const __half* __restrict__ XL = g_Xkl;
    const __half* __restrict__ WH = g_Wh + (size_t)which * DIM * DIM;
    __half* __restrict__ OutH = (which == 0) ? g_Qh : (which == 1) ? g_Kh : g_Vh;

    const int m0B = blockIdx.y * 128;
    const int n0B = blockIdx.x * 128;
    const int m0W = (wid >> 2) * 64;
    const int n0W = (wid & 3) * 32;

    auto load_stage = [&](int buf, int k0) {
        const uint32_t bo = sb + buf * P_STGB;
#pragma unroll
        for (int hp = 0; hp < 2; hp++) {
            int slot = tid + hp * 256;
            int r  = slot >> 2;
            int cc = slot & 3;
            uint32_t d = bo + r * PROWB + cc * 16;
            size_t ga = (size_t)(m0B + r) * DIM + k0 + cc * 8;
            cpa16(d + 0 * PMATB, XH + ga);
            if (two_pass) cpa16(d + 1 * PMATB, XL + ga);
            cpa16(d + 2 * PMATB, WH + (size_t)(n0B + r) * DIM + k0 + cc * 8);
        }
    };

    float acc[4][4][4];
#pragma unroll
    for (int mt = 0; mt < 4; mt++)
#pragma unroll
        for (int nt = 0; nt < 4; nt++)
#pragma unroll
            for (int q = 0; q < 4; q++) acc[mt][nt][q] = 0.f;

    const int aoff = (m0W + (lane & 15)) * PROWB + (lane >> 4) * 16;
    const int boff = (n0W + (grp >> 1) * 8 + (lane & 7)) * PROWB + (grp & 1) * 16;

    load_stage(0, 0);  CP_COMMIT();
    load_stage(1, 32); CP_COMMIT();

    for (int it = 0; it < 32; it++) {
        CP_WAIT1();
        __syncthreads();
        const uint32_t bo = sb + (it & 1) * P_STGB;
        const uint32_t aH = bo + 0 * PMATB + aoff;
        const uint32_t aL = bo + 1 * PMATB + aoff;
        const uint32_t bH = bo + 2 * PMATB + boff;

#pragma unroll
        for (int ks = 0; ks < 2; ks++) {
            const int kb = ks * 32;
            uint32_t ah[4][4], al[4][4], bh[4][2];
#pragma unroll
            for (int mt = 0; mt < 4; mt++) {
                ldsm4(ah[mt], aH + mt * 16 * PROWB + kb);
                if (two_pass) ldsm4(al[mt], aL + mt * 16 * PROWB + kb);
            }
#pragma unroll
            for (int bt = 0; bt < 2; bt++) {
                uint32_t t[4];
                ldsm4(t, bH + bt * 16 * PROWB + kb);
                bh[bt * 2][0] = t[0]; bh[bt * 2][1] = t[1];
                bh[bt * 2 + 1][0] = t[2]; bh[bt * 2 + 1][1] = t[3];
            }
#pragma unroll
            for (int mt = 0; mt < 4; mt++)
#pragma unroll
                for (int nt = 0; nt < 4; nt++)
                    mma16816(acc[mt][nt], ah[mt], bh[nt]);
            if (two_pass) {
#pragma unroll
                for (int mt = 0; mt < 4; mt++)
#pragma unroll
                    for (int nt = 0; nt < 4; nt++)
                        mma16816(acc[mt][nt], al[mt], bh[nt]);
            }
        }
        __syncthreads();
        const int ns = (it + 2 < 32) ? (it + 2) : 31;
        load_stage((it + 2) & 1, ns * 32);
        CP_COMMIT();
    }

    const int rr  = lane >> 2;
    const int cc2 = (lane & 3) * 2;
#pragma unroll
    for (int mt = 0; mt < 4; mt++) {
#pragma unroll
        for (int hp = 0; hp < 2; hp++) {
            const int m = m0B + m0W + mt * 16 + rr + hp * 8;
            const int n = m >> 11;
            const int l = m & 2047;
            const float ksc = (which == 1) ? g_rscale[n] * 1.44269504f : 1.0f;
            const size_t rowb = ((size_t)(n * NH) * LQ + l) * DH;
#pragma unroll
            for (int nt = 0; nt < 4; nt++) {
                const int j  = n0B + n0W + nt * 8 + cc2;
                const int h  = j >> 6;
                const int dh = j & 63;
                *reinterpret_cast<uint32_t*>(&OutH[rowb + (size_t)h * LQ * DH + dh]) =
                    h2_only(acc[mt][nt][hp * 2 + 0] * ksc,
                            acc[mt][nt][hp * 2 + 1] * ksc);
            }
        }
    }
}

// ================= FA2 attention, fp16 HMMA ================================
// S = 1-pass (Qh·Kh; K pre-scaled by rscale*log2e; exp -> ex2).
// PV = 1-pass (Ph·Vh).  l accumulated via ones-column MMA (9th o tile).
// KV stage: Kh, Vh.  Occupancy 2.  LPT block order.
#define ASTR    72
#define AROWB   (ASTR * 2)               // 144 bytes
#define AQB     (128 * AROWB)            // 18432 (Qh only)
#define AKB     (64 * AROWB)             // 9216 per K/V matrix
#define ASTG0   AQB                      // 18432
#define ASTGB   (2 * AKB)                // 18432 per stage (Kh,Vh)
#define ASMEM   (ASTG0 + 2 * ASTGB)      // 55296

#define ONES2   0x3C003C00u              // half2(1.0, 1.0)

__global__ __launch_bounds__(256, 2)
void attn_mma_kernel(float* __restrict__ out) {
    extern __shared__ char smem[];
    const uint32_t sb = smem_u32(smem);

    const int tid  = threadIdx.x;
    const int wid  = tid >> 5;
    const int lane = tid & 31;
    const int grp  = lane >> 3;

    // LPT: heavy (large q0) blocks launch first
    const int q0 = (gridDim.x - 1 - blockIdx.x) * 128;
    const int nh = blockIdx.y;
    const int n  = nh >> 4;
    const int h  = nh & 15;

    const int valid = g_valid[n];
    const int kend  = min(valid, q0 + 128);
    const int nkb   = (kend + 63) >> 6;   // >= 2 always (valid >= 1024)

    const size_t base = (size_t)nh * LK * DH;
    const __half* __restrict__ Qhb = g_Qh + base;
    const __half* __restrict__ Khb = g_Kh + base;
    const __half* __restrict__ Vhb = g_Vh + base;

    auto load_q = [&]() {
#pragma unroll
        for (int i = 0; i < 4; i++) {
            int c  = tid + i * 256;
            int r  = c >> 3;
            int cc = c & 7;
            cpa16(sb + r * AROWB + cc * 16, Qhb + (size_t)(q0 + r) * DH + cc * 8);
        }
    };
    auto load_kv = [&](int buf, int kb) {
        const int k0 = kb * 64;
        const uint32_t so = sb + ASTG0 + buf * ASTGB;
#pragma unroll
        for (int i = 0; i < 4; i++) {
            int c   = tid + i * 256;
            int mat = c >> 9;                 // 0:Kh 1:Vh
            int r   = (c >> 3) & 63;
            int cc  = c & 7;
            const __half* src = (mat == 0) ? Khb : Vhb;
            src += (size_t)(k0 + r) * DH + cc * 8;
            cpa16(so + mat * AKB + r * AROWB + cc * 16, src);
        }
    };

    const int wq0 = wid * 16;
    const int r0  = lane >> 2;
    const int qr0 = q0 + wq0 + r0;
    const int qr1 = qr0 + 8;

    const int qoff = (wq0 + (lane & 15)) * AROWB + (lane >> 4) * 16;
    const int koff = ((grp >> 1) * 8 + (lane & 7)) * AROWB + (grp & 1) * 16;
    const int voff = ((grp & 1) * 8 + (lane & 7)) * AROWB + (grp >> 1) * 16;

    uint32_t qh[4][4];
    float o[9][4];                        // [8] = ones-column (row sums -> l)
#pragma unroll
    for (int nt = 0; nt < 9; nt++)
#pragma unroll
        for (int q = 0; q < 4; q++) o[nt][q] = 0.f;
    float m0 = -1e30f, m1 = -1e30f;

    const uint32_t bones[2] = {ONES2, ONES2};

    load_q();
    load_kv(0, 0);
    CP_COMMIT();
    load_kv(1, 1);
    CP_COMMIT();

    for (int kb = 0; kb < nkb; kb++) {
        CP_WAIT1();
        __syncthreads();
        const int k0 = kb * 64;
        const uint32_t so = sb + ASTG0 + (kb & 1) * ASTGB;

        if (kb == 0) {
#pragma unroll
            for (int kt = 0; kt < 4; kt++)
                ldsm4(qh[kt], sb + qoff + kt * 32);
        }

        // ---- S = Q K^T (1-pass; K carries rscale*log2e) ----
        float sc[8][4];
#pragma unroll
        for (int nt = 0; nt < 8; nt++)
#pragma unroll
            for (int q = 0; q < 4; q++) sc[nt][q] = 0.f;

#pragma unroll
        for (int kt = 0; kt < 4; kt++) {
            uint32_t bh[8][2];
#pragma unroll
            for (int bt = 0; bt < 4; bt++) {
                uint32_t t[4];
                ldsm4(t, so + 0 * AKB + koff + bt * 16 * AROWB + kt * 32);
                bh[bt * 2][0] = t[0]; bh[bt * 2][1] = t[1];
                bh[bt * 2 + 1][0] = t[2]; bh[bt * 2 + 1][1] = t[3];
            }
#pragma unroll
            for (int nt = 0; nt < 8; nt++)
                mma16816(sc[nt], qh[kt], bh[nt]);
        }

        // ---- mask only when this warp's rows intersect causal/pad boundary ----
        if (k0 + 63 > q0 + wq0 || k0 + 64 > valid) {
#pragma unroll
            for (int nt = 0; nt < 8; nt++) {
                const int kc = k0 + nt * 8 + (lane & 3) * 2;
                if (kc     > qr0 || kc     >= valid) sc[nt][0] = -1e30f;
                if (kc + 1 > qr0 || kc + 1 >= valid) sc[nt][1] = -1e30f;
                if (kc     > qr1 || kc     >= valid) sc[nt][2] = -1e30f;
                if (kc + 1 > qr1 || kc + 1 >= valid) sc[nt][3] = -1e30f;
            }
        }

        // ---- online softmax (base-2); l lives in o[8] via ones-MMA ----
        float mx0 = -1e30f, mx1 = -1e30f;
#pragma unroll
        for (int nt = 0; nt < 8; nt++) {
            mx0 = fmaxf(mx0, fmaxf(sc[nt][0], sc[nt][1]));
            mx1 = fmaxf(mx1, fmaxf(sc[nt][2], sc[nt][3]));
        }
        mx0 = fmaxf(mx0, __shfl_xor_sync(0xffffffffu, mx0, 1));
        mx0 = fmaxf(mx0, __shfl_xor_sync(0xffffffffu, mx0, 2));
        mx1 = fmaxf(mx1, __shfl_xor_sync(0xffffffffu, mx1, 1));
        mx1 = fmaxf(mx1, __shfl_xor_sync(0xffffffffu, mx1, 2));
        const float mn0 = fmaxf(m0, mx0);
        const float mn1 = fmaxf(m1, mx1);
        const float f0 = ex2(m0 - mn0);
        const float f1 = ex2(m1 - mn1);
        m0 = mn0; m1 = mn1;

#pragma unroll
        for (int nt = 0; nt < 8; nt++) {
            sc[nt][0] = ex2(sc[nt][0] - mn0);
            sc[nt][1] = ex2(sc[nt][1] - mn0);
            sc[nt][2] = ex2(sc[nt][2] - mn1);
            sc[nt][3] = ex2(sc[nt][3] - mn1);
        }

#pragma unroll
        for (int nt = 0; nt < 9; nt++) {
            o[nt][0] *= f0; o[nt][1] *= f0;
            o[nt][2] *= f1; o[nt][3] *= f1;
        }

        // ---- O += P V (1-pass) + l += P·1 (constant ones B fragment) ----
#pragma unroll
        for (int kt = 0; kt < 4; kt++) {
            uint32_t ah[4];
            ah[0] = h2_only(sc[2 * kt][0],     sc[2 * kt][1]);
            ah[1] = h2_only(sc[2 * kt][2],     sc[2 * kt][3]);
            ah[2] = h2_only(sc[2 * kt + 1][0], sc[2 * kt + 1][1]);
            ah[3] = h2_only(sc[2 * kt + 1][2], sc[2 * kt + 1][3]);

            uint32_t bvh[8][2];
#pragma unroll
            for (int jp = 0; jp < 4; jp++) {
                uint32_t t[4];
                ldsm4t(t, so + 1 * AKB + voff + kt * 16 * AROWB + jp * 32);
                bvh[jp * 2][0] = t[0]; bvh[jp * 2][1] = t[1];
                bvh[jp * 2 + 1][0] = t[2]; bvh[jp * 2 + 1][1] = t[3];
            }
#pragma unroll
            for (int nt = 0; nt < 8; nt++)
                mma16816(o[nt], ah, bvh[nt]);
            mma16816(o[8], ah, bones);
        }

        __syncthreads();
        const int nb2 = (kb + 2 < nkb) ? (kb + 2) : (nkb - 1);
        load_kv((kb + 2) & 1, nb2);
        CP_COMMIT();
    }

    // ---- normalize + store (l = o[8]; every column holds the row sum) ----
    const float il0 = 1.0f / o[8][0];
    const float il1 = 1.0f / o[8][2];
    const int lr0 = q0 + wq0 + r0;
    float* orow0 = &out[((size_t)n * LQ + lr0) * DIM + h * DH];
    float* orow1 = &out[((size_t)n * LQ + lr0 + 8) * DIM + h * DH];
#pragma unroll
    for (int nt = 0; nt < 8; nt++) {
        const int dh = nt * 8 + (lane & 3) * 2;
        float2 v0; v0.x = o[nt][0] * il0; v0.y = o[nt][1] * il0;
        float2 v1; v1.x = o[nt][2] * il1; v1.y = o[nt][3] * il1;
        *reinterpret_cast<float2*>(orow0 + dh) = v0;
        *reinterpret_cast<float2*>(orow1 + dh) = v1;
    }
}

// ----------------------------- launcher -------------------------------------
extern "C" void kernel_launch(void* const* d_in, const int* in_sizes, int n_in,
                              void* d_out, int out_size) {
    const float* query = (const float*)d_in[0];
    const float* key   = (const float*)d_in[1];
    const float* Wq    = (const float*)d_in[2];
    const float* Wk    = (const float*)d_in[3];
    const float* Wv    = (const float*)d_in[4];
    const void* pad = (in_sizes[6] == NB * LK) ? d_in[6]
                    : (in_sizes[5] == NB * LK) ? d_in[5]
                    : d_in[6];
    float* out = (float*)d_out;

    prep_kernel<<<PREP_BLOCKS, 256>>>(query, key, Wq, Wk, Wv, pad);

    cudaFuncSetAttribute(proj_kernel,
                         cudaFuncAttributeMaxDynamicSharedMemorySize, P_SMEM);
    dim3 pgrid(DIM / 128, (NB * LQ) / 128, 3);    // (8, 64, 3)
    proj_kernel<<<pgrid, 256, P_SMEM>>>(0);

    cudaFuncSetAttribute(attn_mma_kernel,
                         cudaFuncAttributeMaxDynamicSharedMemorySize, ASMEM);
    dim3 agrid(LQ / 128, NB * NH);
    attn_mma_kernel<<<agrid, 256, ASMEM>>>(out);
}

// round 15
// speedup vs baseline: 1.0831x; 1.0831x over previous
#include <cuda_runtime.h>
#include <cuda_fp16.h>
#include <math.h>
#include <stdint.h>

#define NB   4
#define LQ   2048
#define LK   2048
#define DIM  1024
#define NH   16
#define DH   64

// ---------------- scratch (static device arrays; no allocation) -------------
__device__ __half g_Xqh[NB * LQ * DIM];
__device__ __half g_Xkh[NB * LK * DIM];
__device__ __half g_Xkl[NB * LK * DIM];
__device__ __half g_Wh[3 * DIM * DIM];
__device__ __half g_Qh[NB * NH * LQ * DH];
__device__ __half g_Kh[NB * NH * LK * DH];   // pre-scaled by rscale[n]*log2(e)
__device__ __half g_Vh[NB * NH * LK * DH];
__device__ int   g_valid[NB];
__device__ float g_rscale[NB];

// ========================= low-level helpers ================================
__device__ __forceinline__ uint32_t smem_u32(const void* p) {
    uint32_t a;
    asm("{ .reg .u64 t; cvta.to.shared.u64 t, %1; cvt.u32.u64 %0, t; }"
        : "=r"(a) : "l"(p));
    return a;
}

__device__ __forceinline__ float ex2(float x) {
    float r;
    asm("ex2.approx.f32 %0, %1;" : "=f"(r) : "f"(x));
    return r;
}

__device__ __forceinline__ void cpa16(uint32_t dst, const void* src) {
    asm volatile("cp.async.cg.shared.global [%0], [%1], 16;"
                 :: "r"(dst), "l"(src) : "memory");
}
#define CP_COMMIT() asm volatile("cp.async.commit_group;" ::: "memory")
#define CP_WAIT1()  asm volatile("cp.async.wait_group 1;" ::: "memory")

__device__ __forceinline__ void ldsm4(uint32_t* r, uint32_t addr) {
    asm volatile("ldmatrix.sync.aligned.m8n8.x4.shared.b16 {%0,%1,%2,%3}, [%4];"
                 : "=r"(r[0]), "=r"(r[1]), "=r"(r[2]), "=r"(r[3]) : "r"(addr));
}
__device__ __forceinline__ void ldsm4t(uint32_t* r, uint32_t addr) {
    asm volatile("ldmatrix.sync.aligned.m8n8.x4.trans.shared.b16 {%0,%1,%2,%3}, [%4];"
                 : "=r"(r[0]), "=r"(r[1]), "=r"(r[2]), "=r"(r[3]) : "r"(addr));
}

__device__ __forceinline__ void mma16816(float* d, const uint32_t* a,
                                         const uint32_t* b) {
    asm volatile(
        "mma.sync.aligned.m16n8k16.row.col.f32.f16.f16.f32 "
        "{%0,%1,%2,%3}, {%4,%5,%6,%7}, {%8,%9}, {%0,%1,%2,%3};"
        : "+f"(d[0]), "+f"(d[1]), "+f"(d[2]), "+f"(d[3])
        : "r"(a[0]), "r"(a[1]), "r"(a[2]), "r"(a[3]), "r"(b[0]), "r"(b[1]));
}

__device__ __forceinline__ void hilo_h2(float a, float b, uint32_t& h, uint32_t& l) {
    __half ha = __float2half_rn(a);
    __half hb = __float2half_rn(b);
    float ra = a - __half2float(ha);
    float rb = b - __half2float(hb);
    __half2 H = __halves2half2(ha, hb);
    __half2 L = __floats2half2_rn(ra, rb);
    h = *reinterpret_cast<uint32_t*>(&H);
    l = *reinterpret_cast<uint32_t*>(&L);
}

__device__ __forceinline__ uint32_t h2_only(float a, float b) {
    __half2 H = __floats2half2_rn(a, b);
    return *reinterpret_cast<uint32_t*>(&H);
}

// ============ fused prep: valid-count + all f32->fp16 conversions ============
// Region map (256-thread blocks):
//   [0, 4096)        : query -> g_Xqh (hi only)
//   [4096, 8192)     : key   -> g_Xkh + g_Xkl (hi/lo)
//   [8192, 9728)     : W q/k/v -> g_Wh (hi only)
//   [9728, 9732)     : valid count (4 blocks)
#define PREP_BLOCKS 9732

__global__ void prep_kernel(const float* __restrict__ query,
                            const float* __restrict__ key,
                            const float* __restrict__ Wq,
                            const float* __restrict__ Wk,
                            const float* __restrict__ Wv,
                            const void*  __restrict__ pad) {
    const int b = blockIdx.x;
    const int tid = threadIdx.x;

    if (b < 4096) {                        // query hi
        int i = (b * 256 + tid) * 8;
        float4 a = *reinterpret_cast<const float4*>(query + i);
        float4 c = *reinterpret_cast<const float4*>(query + i + 4);
        uint4 H;
        H.x = h2_only(a.x, a.y); H.y = h2_only(a.z, a.w);
        H.z = h2_only(c.x, c.y); H.w = h2_only(c.z, c.w);
        *reinterpret_cast<uint4*>(g_Xqh + i) = H;
        return;
    }
    if (b < 8192) {                        // key hi/lo
        int i = ((b - 4096) * 256 + tid) * 8;
        float4 a = *reinterpret_cast<const float4*>(key + i);
        float4 c = *reinterpret_cast<const float4*>(key + i + 4);
        uint4 H, L;
        hilo_h2(a.x, a.y, H.x, L.x);
        hilo_h2(a.z, a.w, H.y, L.y);
        hilo_h2(c.x, c.y, H.z, L.z);
        hilo_h2(c.z, c.w, H.w, L.w);
        *reinterpret_cast<uint4*>(g_Xkh + i) = H;
        *reinterpret_cast<uint4*>(g_Xkl + i) = L;
        return;
    }
    if (b < 9728) {                        // weights hi
        int wi = (b - 8192) / 512;         // 0:Wq 1:Wk 2:Wv
        const float* W = (wi == 0) ? Wq : (wi == 1) ? Wk : Wv;
        int i = (((b - 8192) & 511) * 256 + tid) * 8;
        float4 a = *reinterpret_cast<const float4*>(W + i);
        float4 c = *reinterpret_cast<const float4*>(W + i + 4);
        uint4 H;
        H.x = h2_only(a.x, a.y); H.y = h2_only(a.z, a.w);
        H.z = h2_only(c.x, c.y); H.w = h2_only(c.z, c.w);
        *reinterpret_cast<uint4*>(g_Wh + (size_t)wi * DIM * DIM + i) = H;
        return;
    }

    // ---- valid count (4 blocks; result consumed only by later kernels) ----
    const int n = b - 9728;
    __shared__ int red[256];

    const unsigned* w = (const unsigned*)pad;
    int f = 0;
    for (int i = tid; i < 2048; i += 256) {
        unsigned v = w[i];
        if (v == 0x3F800000u) f |= 4;
        else if (v == 0x00000001u) f |= 2;
        else if (v == 0x01000000u || v == 0x01010000u ||
                 v == 0x01010100u || v == 0x01010101u) f |= 1;
    }
    red[tid] = f;
    __syncthreads();
    for (int s = 128; s > 0; s >>= 1) {
        if (tid < s) red[tid] |= red[tid + s];
        __syncthreads();
    }
    const int fl = red[0];
    const int layout = (fl & 1) ? 0 : ((fl & 4) ? 2 : 1);
    __syncthreads();

    int c = 0;
    if (layout == 0) {
        const unsigned char* p = (const unsigned char*)pad;
        for (int j = tid; j < LK; j += 256) c += (p[n * LK + j] == 0);
    } else if (layout == 1) {
        const int* p = (const int*)pad;
        for (int j = tid; j < LK; j += 256) c += (p[n * LK + j] == 0);
    } else {
        const float* p = (const float*)pad;
        for (int j = tid; j < LK; j += 256) c += (p[n * LK + j] == 0.0f);
    }
    red[tid] = c;
    __syncthreads();
    for (int s = 128; s > 0; s >>= 1) {
        if (tid < s) red[tid] += red[tid + s];
        __syncthreads();
    }
    if (tid == 0) {
        g_valid[n]  = red[0];
        g_rscale[n] = rsqrtf((float)red[0]);
    }
}

// ======================= shared proj constants ===============================
#define PSTR    40
#define PROWB   (PSTR * 2)               // 80 bytes
#define PMATB   (128 * PROWB)            // 10240 bytes per matrix tile

// ============ Q/K projection: 1-pass, 2 matrices/stage, occupancy 2 ==========
#define QK_STGB (2 * PMATB)              // 20480 per stage (Ah, Bh)
#define QK_SMEM (2 * QK_STGB)            // 40960

__global__ __launch_bounds__(256, 2)
void qk_proj_kernel(int dummy) {
    extern __shared__ char smem[];
    const uint32_t sb = smem_u32(smem);

    const int tid  = threadIdx.x;
    const int wid  = tid >> 5;
    const int lane = tid & 31;
    const int grp  = lane >> 3;

    const int which = blockIdx.z;        // 0:Q 1:K
    const __half* __restrict__ XH = (which == 0) ? g_Xqh : g_Xkh;
    const __half* __restrict__ WH = g_Wh + (size_t)which * DIM * DIM;
    __half* __restrict__ OutH = (which == 0) ? g_Qh : g_Kh;

    const int m0B = blockIdx.y * 128;
    const int n0B = blockIdx.x * 128;
    const int m0W = (wid >> 2) * 64;
    const int n0W = (wid & 3) * 32;

    auto load_stage = [&](int buf, int k0) {
        const uint32_t bo = sb + buf * QK_STGB;
#pragma unroll
        for (int hp = 0; hp < 2; hp++) {
            int slot = tid + hp * 256;
            int r  = slot >> 2;
            int cc = slot & 3;
            uint32_t d = bo + r * PROWB + cc * 16;
            cpa16(d + 0 * PMATB, XH + (size_t)(m0B + r) * DIM + k0 + cc * 8);
            cpa16(d + 1 * PMATB, WH + (size_t)(n0B + r) * DIM + k0 + cc * 8);
        }
    };

    float acc[4][4][4];
#pragma unroll
    for (int mt = 0; mt < 4; mt++)
#pragma unroll
        for (int nt = 0; nt < 4; nt++)
#pragma unroll
            for (int q = 0; q < 4; q++) acc[mt][nt][q] = 0.f;

    const int aoff = (m0W + (lane & 15)) * PROWB + (lane >> 4) * 16;
    const int boff = (n0W + (grp >> 1) * 8 + (lane & 7)) * PROWB + (grp & 1) * 16;

    load_stage(0, 0);  CP_COMMIT();
    load_stage(1, 32); CP_COMMIT();

    for (int it = 0; it < 32; it++) {
        CP_WAIT1();
        __syncthreads();
        const uint32_t bo = sb + (it & 1) * QK_STGB;
        const uint32_t aH = bo + 0 * PMATB + aoff;
        const uint32_t bH = bo + 1 * PMATB + boff;

#pragma unroll
        for (int ks = 0; ks < 2; ks++) {
            const int kb = ks * 32;
            uint32_t ah[4][4], bh[4][2];
#pragma unroll
            for (int mt = 0; mt < 4; mt++)
                ldsm4(ah[mt], aH + mt * 16 * PROWB + kb);
#pragma unroll
            for (int bt = 0; bt < 2; bt++) {
                uint32_t t[4];
                ldsm4(t, bH + bt * 16 * PROWB + kb);
                bh[bt * 2][0] = t[0]; bh[bt * 2][1] = t[1];
                bh[bt * 2 + 1][0] = t[2]; bh[bt * 2 + 1][1] = t[3];
            }
#pragma unroll
            for (int mt = 0; mt < 4; mt++)
#pragma unroll
                for (int nt = 0; nt < 4; nt++)
                    mma16816(acc[mt][nt], ah[mt], bh[nt]);
        }
        __syncthreads();
        const int ns = (it + 2 < 32) ? (it + 2) : 31;
        load_stage((it + 2) & 1, ns * 32);
        CP_COMMIT();
    }

    const int rr  = lane >> 2;
    const int cc2 = (lane & 3) * 2;
#pragma unroll
    for (int mt = 0; mt < 4; mt++) {
#pragma unroll
        for (int hp = 0; hp < 2; hp++) {
            const int m = m0B + m0W + mt * 16 + rr + hp * 8;
            const int n = m >> 11;
            const int l = m & 2047;
            const float ksc = (which == 1) ? g_rscale[n] * 1.44269504f : 1.0f;
            const size_t rowb = ((size_t)(n * NH) * LQ + l) * DH;
#pragma unroll
            for (int nt = 0; nt < 4; nt++) {
                const int j  = n0B + n0W + nt * 8 + cc2;
                const int h  = j >> 6;
                const int dh = j & 63;
                *reinterpret_cast<uint32_t*>(&OutH[rowb + (size_t)h * LQ * DH + dh]) =
                    h2_only(acc[mt][nt][hp * 2 + 0] * ksc,
                            acc[mt][nt][hp * 2 + 1] * ksc);
            }
        }
    }
}

// ============ V projection: 2-pass (AhBh + AlBh), 3 mats/stage, occ 2 ========
#define V_STGB  (3 * PMATB)              // 30720 per stage (Ah, Al, Bh)
#define V_SMEM  (2 * V_STGB)             // 61440

__global__ __launch_bounds__(256, 2)
void v_proj_kernel(int dummy) {
    extern __shared__ char smem[];
    const uint32_t sb = smem_u32(smem);

    const int tid  = threadIdx.x;
    const int wid  = tid >> 5;
    const int lane = tid & 31;
    const int grp  = lane >> 3;

    const __half* __restrict__ XH = g_Xkh;
    const __half* __restrict__ XL = g_Xkl;
    const __half* __restrict__ WH = g_Wh + 2 * (size_t)DIM * DIM;

    const int m0B = blockIdx.y * 128;
    const int n0B = blockIdx.x * 128;
    const int m0W = (wid >> 2) * 64;
    const int n0W = (wid & 3) * 32;

    auto load_stage = [&](int buf, int k0) {
        const uint32_t bo = sb + buf * V_STGB;
#pragma unroll
        for (int hp = 0; hp < 2; hp++) {
            int slot = tid + hp * 256;
            int r  = slot >> 2;
            int cc = slot & 3;
            uint32_t d = bo + r * PROWB + cc * 16;
            size_t ga = (size_t)(m0B + r) * DIM + k0 + cc * 8;
            cpa16(d + 0 * PMATB, XH + ga);
            cpa16(d + 1 * PMATB, XL + ga);
            cpa16(d + 2 * PMATB, WH + (size_t)(n0B + r) * DIM + k0 + cc * 8);
        }
    };

    float acc[4][4][4];
#pragma unroll
    for (int mt = 0; mt < 4; mt++)
#pragma unroll
        for (int nt = 0; nt < 4; nt++)
#pragma unroll
            for (int q = 0; q < 4; q++) acc[mt][nt][q] = 0.f;

    const int aoff = (m0W + (lane & 15)) * PROWB + (lane >> 4) * 16;
    const int boff = (n0W + (grp >> 1) * 8 + (lane & 7)) * PROWB + (grp & 1) * 16;

    load_stage(0, 0);  CP_COMMIT();
    load_stage(1, 32); CP_COMMIT();

    for (int it = 0; it < 32; it++) {
        CP_WAIT1();
        __syncthreads();
        const uint32_t bo = sb + (it & 1) * V_STGB;
        const uint32_t aH = bo + 0 * PMATB + aoff;
        const uint32_t aL = bo + 1 * PMATB + aoff;
        const uint32_t bH = bo + 2 * PMATB + boff;

#pragma unroll
        for (int ks = 0; ks < 2; ks++) {
            const int kb = ks * 32;
            uint32_t ah[4][4], al[4][4], bh[4][2];
#pragma unroll
            for (int mt = 0; mt < 4; mt++) {
                ldsm4(ah[mt], aH + mt * 16 * PROWB + kb);
                ldsm4(al[mt], aL + mt * 16 * PROWB + kb);
            }
#pragma unroll
            for (int bt = 0; bt < 2; bt++) {
                uint32_t t[4];
                ldsm4(t, bH + bt * 16 * PROWB + kb);
                bh[bt * 2][0] = t[0]; bh[bt * 2][1] = t[1];
                bh[bt * 2 + 1][0] = t[2]; bh[bt * 2 + 1][1] = t[3];
            }
#pragma unroll
            for (int mt = 0; mt < 4; mt++)
#pragma unroll
                for (int nt = 0; nt < 4; nt++) {
                    mma16816(acc[mt][nt], ah[mt], bh[nt]);
                    mma16816(acc[mt][nt], al[mt], bh[nt]);
                }
        }
        __syncthreads();
        const int ns = (it + 2 < 32) ? (it + 2) : 31;
        load_stage((it + 2) & 1, ns * 32);
        CP_COMMIT();
    }

    const int rr  = lane >> 2;
    const int cc2 = (lane & 3) * 2;
#pragma unroll
    for (int mt = 0; mt < 4; mt++) {
#pragma unroll
        for (int hp = 0; hp < 2; hp++) {
            const int m = m0B + m0W + mt * 16 + rr + hp * 8;
            const int n = m >> 11;
            const int l = m & 2047;
            const size_t rowb = ((size_t)(n * NH) * LQ + l) * DH;
#pragma unroll
            for (int nt = 0; nt < 4; nt++) {
                const int j  = n0B + n0W + nt * 8 + cc2;
                const int h  = j >> 6;
                const int dh = j & 63;
                *reinterpret_cast<uint32_t*>(&g_Vh[rowb + (size_t)h * LQ * DH + dh]) =
                    h2_only(acc[mt][nt][hp * 2 + 0], acc[mt][nt][hp * 2 + 1]);
            }
        }
    }
}

// ================= FA2 attention, fp16 HMMA ================================
// S = 1-pass (Qh·Kh; K pre-scaled by rscale*log2e; exp -> ex2).
// PV = 1-pass (Ph·Vh).  KV stage: Kh, Vh.  Occupancy 2.  LPT block order.
#define ASTR    72
#define AROWB   (ASTR * 2)               // 144 bytes
#define AQB     (128 * AROWB)            // 18432 (Qh only)
#define AKB     (64 * AROWB)             // 9216 per K/V matrix
#define ASTG0   AQB                      // 18432
#define ASTGB   (2 * AKB)                // 18432 per stage (Kh,Vh)
#define ASMEM   (ASTG0 + 2 * ASTGB)      // 55296

__global__ __launch_bounds__(256, 2)
void attn_mma_kernel(float* __restrict__ out) {
    extern __shared__ char smem[];
    const uint32_t sb = smem_u32(smem);

    const int tid  = threadIdx.x;
    const int wid  = tid >> 5;
    const int lane = tid & 31;
    const int grp  = lane >> 3;

    // LPT: heavy (large q0) blocks launch first
    const int q0 = (gridDim.x - 1 - blockIdx.x) * 128;
    const int nh = blockIdx.y;
    const int n  = nh >> 4;
    const int h  = nh & 15;

    const int valid = g_valid[n];
    const int kend  = min(valid, q0 + 128);
    const int nkb   = (kend + 63) >> 6;   // >= 2 always (valid >= 1024)

    const size_t base = (size_t)nh * LK * DH;
    const __half* __restrict__ Qhb = g_Qh + base;
    const __half* __restrict__ Khb = g_Kh + base;
    const __half* __restrict__ Vhb = g_Vh + base;

    auto load_q = [&]() {
#pragma unroll
        for (int i = 0; i < 4; i++) {
            int c  = tid + i * 256;
            int r  = c >> 3;
            int cc = c & 7;
            cpa16(sb + r * AROWB + cc * 16, Qhb + (size_t)(q0 + r) * DH + cc * 8);
        }
    };
    auto load_kv = [&](int buf, int kb) {
        const int k0 = kb * 64;
        const uint32_t so = sb + ASTG0 + buf * ASTGB;
#pragma unroll
        for (int i = 0; i < 4; i++) {
            int c   = tid + i * 256;
            int mat = c >> 9;                 // 0:Kh 1:Vh
            int r   = (c >> 3) & 63;
            int cc  = c & 7;
            const __half* src = (mat == 0) ? Khb : Vhb;
            src += (size_t)(k0 + r) * DH + cc * 8;
            cpa16(so + mat * AKB + r * AROWB + cc * 16, src);
        }
    };

    const int wq0 = wid * 16;
    const int r0  = lane >> 2;
    const int qr0 = q0 + wq0 + r0;
    const int qr1 = qr0 + 8;

    const int qoff = (wq0 + (lane & 15)) * AROWB + (lane >> 4) * 16;
    const int koff = ((grp >> 1) * 8 + (lane & 7)) * AROWB + (grp & 1) * 16;
    const int voff = ((grp & 1) * 8 + (lane & 7)) * AROWB + (grp >> 1) * 16;

    uint32_t qh[4][4];
    float o[8][4];
#pragma unroll
    for (int nt = 0; nt < 8; nt++)
#pragma unroll
        for (int q = 0; q < 4; q++) o[nt][q] = 0.f;
    float m0 = -1e30f, m1 = -1e30f, l0 = 0.f, l1 = 0.f;

    load_q();
    load_kv(0, 0);
    CP_COMMIT();
    load_kv(1, (nkb > 1) ? 1 : 0);
    CP_COMMIT();

    for (int kb = 0; kb < nkb; kb++) {
        CP_WAIT1();
        __syncthreads();
        const int k0 = kb * 64;
        const uint32_t so = sb + ASTG0 + (kb & 1) * ASTGB;

        if (kb == 0) {
#pragma unroll
            for (int kt = 0; kt < 4; kt++)
                ldsm4(qh[kt], sb + qoff + kt * 32);
        }

        // ---- S = Q K^T (1-pass; K carries rscale*log2e) ----
        float sc[8][4];
#pragma unroll
        for (int nt = 0; nt < 8; nt++)
#pragma unroll
            for (int q = 0; q < 4; q++) sc[nt][q] = 0.f;

#pragma unroll
        for (int kt = 0; kt < 4; kt++) {
            uint32_t bh[8][2];
#pragma unroll
            for (int bt = 0; bt < 4; bt++) {
                uint32_t t[4];
                ldsm4(t, so + 0 * AKB + koff + bt * 16 * AROWB + kt * 32);
                bh[bt * 2][0] = t[0]; bh[bt * 2][1] = t[1];
                bh[bt * 2 + 1][0] = t[2]; bh[bt * 2 + 1][1] = t[3];
            }
#pragma unroll
            for (int nt = 0; nt < 8; nt++)
                mma16816(sc[nt], qh[kt], bh[nt]);
        }

        // ---- mask only when this warp's rows intersect causal/pad boundary ----
        if (k0 + 63 > q0 + wq0 || k0 + 64 > valid) {
#pragma unroll
            for (int nt = 0; nt < 8; nt++) {
                const int kc = k0 + nt * 8 + (lane & 3) * 2;
                if (kc     > qr0 || kc     >= valid) sc[nt][0] = -1e30f;
                if (kc + 1 > qr0 || kc + 1 >= valid) sc[nt][1] = -1e30f;
                if (kc     > qr1 || kc     >= valid) sc[nt][2] = -1e30f;
                if (kc + 1 > qr1 || kc + 1 >= valid) sc[nt][3] = -1e30f;
            }
        }

        // ---- online softmax (base-2) ----
        float mx0 = -1e30f, mx1 = -1e30f;
#pragma unroll
        for (int nt = 0; nt < 8; nt++) {
            mx0 = fmaxf(mx0, fmaxf(sc[nt][0], sc[nt][1]));
            mx1 = fmaxf(mx1, fmaxf(sc[nt][2], sc[nt][3]));
        }
        mx0 = fmaxf(mx0, __shfl_xor_sync(0xffffffffu, mx0, 1));
        mx0 = fmaxf(mx0, __shfl_xor_sync(0xffffffffu, mx0, 2));
        mx1 = fmaxf(mx1, __shfl_xor_sync(0xffffffffu, mx1, 1));
        mx1 = fmaxf(mx1, __shfl_xor_sync(0xffffffffu, mx1, 2));
        const float mn0 = fmaxf(m0, mx0);
        const float mn1 = fmaxf(m1, mx1);
        const float f0 = ex2(m0 - mn0);
        const float f1 = ex2(m1 - mn1);
        m0 = mn0; m1 = mn1;

        float s0 = 0.f, s1 = 0.f;
#pragma unroll
        for (int nt = 0; nt < 8; nt++) {
            sc[nt][0] = ex2(sc[nt][0] - mn0);
            sc[nt][1] = ex2(sc[nt][1] - mn0);
            sc[nt][2] = ex2(sc[nt][2] - mn1);
            sc[nt][3] = ex2(sc[nt][3] - mn1);
            s0 += sc[nt][0] + sc[nt][1];
            s1 += sc[nt][2] + sc[nt][3];
        }
        s0 += __shfl_xor_sync(0xffffffffu, s0, 1);
        s0 += __shfl_xor_sync(0xffffffffu, s0, 2);
        s1 += __shfl_xor_sync(0xffffffffu, s1, 1);
        s1 += __shfl_xor_sync(0xffffffffu, s1, 2);
        l0 = l0 * f0 + s0;
        l1 = l1 * f1 + s1;

#pragma unroll
        for (int nt = 0; nt < 8; nt++) {
            o[nt][0] *= f0; o[nt][1] *= f0;
            o[nt][2] *= f1; o[nt][3] *= f1;
        }

        // ---- O += P V (1-pass: Ph x Vh) ----
#pragma unroll
        for (int kt = 0; kt < 4; kt++) {
            uint32_t ah[4];
            ah[0] = h2_only(sc[2 * kt][0],     sc[2 * kt][1]);
            ah[1] = h2_only(sc[2 * kt][2],     sc[2 * kt][3]);
            ah[2] = h2_only(sc[2 * kt + 1][0], sc[2 * kt + 1][1]);
            ah[3] = h2_only(sc[2 * kt + 1][2], sc[2 * kt + 1][3]);

            uint32_t bvh[8][2];
#pragma unroll
            for (int jp = 0; jp < 4; jp++) {
                uint32_t t[4];
                ldsm4t(t, so + 1 * AKB + voff + kt * 16 * AROWB + jp * 32);
                bvh[jp * 2][0] = t[0]; bvh[jp * 2][1] = t[1];
                bvh[jp * 2 + 1][0] = t[2]; bvh[jp * 2 + 1][1] = t[3];
            }
#pragma unroll
            for (int nt = 0; nt < 8; nt++)
                mma16816(o[nt], ah, bvh[nt]);
        }

        __syncthreads();
        const int nb2 = (kb + 2 < nkb) ? (kb + 2) : (nkb - 1);
        load_kv((kb + 2) & 1, nb2);
        CP_COMMIT();
    }

    // ---- normalize + store ----
    const float il0 = 1.0f / l0;
    const float il1 = 1.0f / l1;
    const int lr0 = q0 + wq0 + r0;
    float* orow0 = &out[((size_t)n * LQ + lr0) * DIM + h * DH];
    float* orow1 = &out[((size_t)n * LQ + lr0 + 8) * DIM + h * DH];
#pragma unroll
    for (int nt = 0; nt < 8; nt++) {
        const int dh = nt * 8 + (lane & 3) * 2;
        float2 v0; v0.x = o[nt][0] * il0; v0.y = o[nt][1] * il0;
        float2 v1; v1.x = o[nt][2] * il1; v1.y = o[nt][3] * il1;
        *reinterpret_cast<float2*>(orow0 + dh) = v0;
        *reinterpret_cast<float2*>(orow1 + dh) = v1;
    }
}

// ----------------------------- launcher -------------------------------------
extern "C" void kernel_launch(void* const* d_in, const int* in_sizes, int n_in,
                              void* d_out, int out_size) {
    const float* query = (const float*)d_in[0];
    const float* key   = (const float*)d_in[1];
    const float* Wq    = (const float*)d_in[2];
    const float* Wk    = (const float*)d_in[3];
    const float* Wv    = (const float*)d_in[4];
    const void* pad = (in_sizes[6] == NB * LK) ? d_in[6]
                    : (in_sizes[5] == NB * LK) ? d_in[5]
                    : d_in[6];
    float* out = (float*)d_out;

    prep_kernel<<<PREP_BLOCKS, 256>>>(query, key, Wq, Wk, Wv, pad);

    cudaFuncSetAttribute(qk_proj_kernel,
                         cudaFuncAttributeMaxDynamicSharedMemorySize, QK_SMEM);
    dim3 qkgrid(DIM / 128, (NB * LQ) / 128, 2);   // (8, 64, 2)
    qk_proj_kernel<<<qkgrid, 256, QK_SMEM>>>(0);

    cudaFuncSetAttribute(v_proj_kernel,
                         cudaFuncAttributeMaxDynamicSharedMemorySize, V_SMEM);
    dim3 vgrid(DIM / 128, (NB * LQ) / 128);       // (8, 64)
    v_proj_kernel<<<vgrid, 256, V_SMEM>>>(0);

    cudaFuncSetAttribute(attn_mma_kernel,
                         cudaFuncAttributeMaxDynamicSharedMemorySize, ASMEM);
    dim3 agrid(LQ / 128, NB * NH);
    attn_mma_kernel<<<agrid, 256, ASMEM>>>(out);
}

// round 16
// speedup vs baseline: 1.1069x; 1.0220x over previous
#include <cuda_runtime.h>
#include <cuda_fp16.h>
#include <math.h>
#include <stdint.h>

#define NB   4
#define LQ   2048
#define LK   2048
#define DIM  1024
#define NH   16
#define DH   64

// ---------------- scratch (static device arrays; no allocation) -------------
__device__ __half g_Xqh[NB * LQ * DIM];
__device__ __half g_Xkh[NB * LK * DIM];
__device__ __half g_Xkl[NB * LK * DIM];
__device__ __half g_Wh[3 * DIM * DIM];
__device__ __half g_Qh[NB * NH * LQ * DH];
__device__ __half g_Kh[NB * NH * LK * DH];   // pre-scaled by rscale[n]*log2(e)
__device__ __half g_Vh[NB * NH * LK * DH];
__device__ int   g_valid[NB];
__device__ float g_rscale[NB];

// ========================= low-level helpers ================================
__device__ __forceinline__ uint32_t smem_u32(const void* p) {
    uint32_t a;
    asm("{ .reg .u64 t; cvta.to.shared.u64 t, %1; cvt.u32.u64 %0, t; }"
        : "=r"(a) : "l"(p));
    return a;
}

__device__ __forceinline__ float ex2(float x) {
    float r;
    asm("ex2.approx.f32 %0, %1;" : "=f"(r) : "f"(x));
    return r;
}

__device__ __forceinline__ void cpa16(uint32_t dst, const void* src) {
    asm volatile("cp.async.cg.shared.global [%0], [%1], 16;"
                 :: "r"(dst), "l"(src) : "memory");
}
#define CP_COMMIT() asm volatile("cp.async.commit_group;" ::: "memory")
#define CP_WAIT1()  asm volatile("cp.async.wait_group 1;" ::: "memory")

__device__ __forceinline__ void ldsm4(uint32_t* r, uint32_t addr) {
    asm volatile("ldmatrix.sync.aligned.m8n8.x4.shared.b16 {%0,%1,%2,%3}, [%4];"
                 : "=r"(r[0]), "=r"(r[1]), "=r"(r[2]), "=r"(r[3]) : "r"(addr));
}
__device__ __forceinline__ void ldsm4t(uint32_t* r, uint32_t addr) {
    asm volatile("ldmatrix.sync.aligned.m8n8.x4.trans.shared.b16 {%0,%1,%2,%3}, [%4];"
                 : "=r"(r[0]), "=r"(r[1]), "=r"(r[2]), "=r"(r[3]) : "r"(addr));
}

__device__ __forceinline__ void mma16816(float* d, const uint32_t* a,
                                         const uint32_t* b) {
    asm volatile(
        "mma.sync.aligned.m16n8k16.row.col.f32.f16.f16.f32 "
        "{%0,%1,%2,%3}, {%4,%5,%6,%7}, {%8,%9}, {%0,%1,%2,%3};"
        : "+f"(d[0]), "+f"(d[1]), "+f"(d[2]), "+f"(d[3])
        : "r"(a[0]), "r"(a[1]), "r"(a[2]), "r"(a[3]), "r"(b[0]), "r"(b[1]));
}

__device__ __forceinline__ void hilo_h2(float a, float b, uint32_t& h, uint32_t& l) {
    __half ha = __float2half_rn(a);
    __half hb = __float2half_rn(b);
    float ra = a - __half2float(ha);
    float rb = b - __half2float(hb);
    __half2 H = __halves2half2(ha, hb);
    __half2 L = __floats2half2_rn(ra, rb);
    h = *reinterpret_cast<uint32_t*>(&H);
    l = *reinterpret_cast<uint32_t*>(&L);
}

__device__ __forceinline__ uint32_t h2_only(float a, float b) {
    __half2 H = __floats2half2_rn(a, b);
    return *reinterpret_cast<uint32_t*>(&H);
}

// ============ fused prep: valid-count + all f32->fp16 conversions ============
#define PREP_BLOCKS 9732

__global__ void prep_kernel(const float* __restrict__ query,
                            const float* __restrict__ key,
                            const float* __restrict__ Wq,
                            const float* __restrict__ Wk,
                            const float* __restrict__ Wv,
                            const void*  __restrict__ pad) {
    const int b = blockIdx.x;
    const int tid = threadIdx.x;

    if (b < 4096) {                        // query hi
        int i = (b * 256 + tid) * 8;
        float4 a = *reinterpret_cast<const float4*>(query + i);
        float4 c = *reinterpret_cast<const float4*>(query + i + 4);
        uint4 H;
        H.x = h2_only(a.x, a.y); H.y = h2_only(a.z, a.w);
        H.z = h2_only(c.x, c.y); H.w = h2_only(c.z, c.w);
        *reinterpret_cast<uint4*>(g_Xqh + i) = H;
        return;
    }
    if (b < 8192) {                        // key hi/lo
        int i = ((b - 4096) * 256 + tid) * 8;
        float4 a = *reinterpret_cast<const float4*>(key + i);
        float4 c = *reinterpret_cast<const float4*>(key + i + 4);
        uint4 H, L;
        hilo_h2(a.x, a.y, H.x, L.x);
        hilo_h2(a.z, a.w, H.y, L.y);
        hilo_h2(c.x, c.y, H.z, L.z);
        hilo_h2(c.z, c.w, H.w, L.w);
        *reinterpret_cast<uint4*>(g_Xkh + i) = H;
        *reinterpret_cast<uint4*>(g_Xkl + i) = L;
        return;
    }
    if (b < 9728) {                        // weights hi
        int wi = (b - 8192) / 512;         // 0:Wq 1:Wk 2:Wv
        const float* W = (wi == 0) ? Wq : (wi == 1) ? Wk : Wv;
        int i = (((b - 8192) & 511) * 256 + tid) * 8;
        float4 a = *reinterpret_cast<const float4*>(W + i);
        float4 c = *reinterpret_cast<const float4*>(W + i + 4);
        uint4 H;
        H.x = h2_only(a.x, a.y); H.y = h2_only(a.z, a.w);
        H.z = h2_only(c.x, c.y); H.w = h2_only(c.z, c.w);
        *reinterpret_cast<uint4*>(g_Wh + (size_t)wi * DIM * DIM + i) = H;
        return;
    }

    // ---- valid count (4 blocks) ----
    const int n = b - 9728;
    __shared__ int red[256];

    const unsigned* w = (const unsigned*)pad;
    int f = 0;
    for (int i = tid; i < 2048; i += 256) {
        unsigned v = w[i];
        if (v == 0x3F800000u) f |= 4;
        else if (v == 0x00000001u) f |= 2;
        else if (v == 0x01000000u || v == 0x01010000u ||
                 v == 0x01010100u || v == 0x01010101u) f |= 1;
    }
    red[tid] = f;
    __syncthreads();
    for (int s = 128; s > 0; s >>= 1) {
        if (tid < s) red[tid] |= red[tid + s];
        __syncthreads();
    }
    const int fl = red[0];
    const int layout = (fl & 1) ? 0 : ((fl & 4) ? 2 : 1);
    __syncthreads();

    int c = 0;
    if (layout == 0) {
        const unsigned char* p = (const unsigned char*)pad;
        for (int j = tid; j < LK; j += 256) c += (p[n * LK + j] == 0);
    } else if (layout == 1) {
        const int* p = (const int*)pad;
        for (int j = tid; j < LK; j += 256) c += (p[n * LK + j] == 0);
    } else {
        const float* p = (const float*)pad;
        for (int j = tid; j < LK; j += 256) c += (p[n * LK + j] == 0.0f);
    }
    red[tid] = c;
    __syncthreads();
    for (int s = 128; s > 0; s >>= 1) {
        if (tid < s) red[tid] += red[tid + s];
        __syncthreads();
    }
    if (tid == 0) {
        g_valid[n]  = red[0];
        g_rscale[n] = rsqrtf((float)red[0]);
    }
}

// ======================= shared proj constants (BK=64) =======================
#define PSTR    72
#define PROWB   (PSTR * 2)               // 144 bytes
#define PMATB   (128 * PROWB)            // 18432 bytes per matrix tile (128x64h)

// ============ Q/K projection: 1-pass, 2 matrices/stage, occ 2, BK=64 =========
#define QK_STGB (2 * PMATB)              // 36864 per stage (Ah, Bh)
#define QK_SMEM (2 * QK_STGB)            // 73728

__global__ __launch_bounds__(256, 2)
void qk_proj_kernel(int dummy) {
    extern __shared__ char smem[];
    const uint32_t sb = smem_u32(smem);

    const int tid  = threadIdx.x;
    const int wid  = tid >> 5;
    const int lane = tid & 31;
    const int grp  = lane >> 3;

    const int which = blockIdx.z;        // 0:Q 1:K
    const __half* __restrict__ XH = (which == 0) ? g_Xqh : g_Xkh;
    const __half* __restrict__ WH = g_Wh + (size_t)which * DIM * DIM;
    __half* __restrict__ OutH = (which == 0) ? g_Qh : g_Kh;

    const int m0B = blockIdx.y * 128;
    const int n0B = blockIdx.x * 128;
    const int m0W = (wid >> 2) * 64;
    const int n0W = (wid & 3) * 32;

    // stage: 2 mats x 128 rows x 8 chunks = 2048 chunks -> 8 per thread
    auto load_stage = [&](int buf, int k0) {
        const uint32_t bo = sb + buf * QK_STGB;
#pragma unroll
        for (int i = 0; i < 8; i++) {
            int slot = tid + i * 256;
            int mat = slot >> 10;
            int r   = (slot >> 3) & 127;
            int cc  = slot & 7;
            uint32_t d = bo + mat * PMATB + r * PROWB + cc * 16;
            const __half* src = (mat == 0)
                ? XH + (size_t)(m0B + r) * DIM + k0 + cc * 8
                : WH + (size_t)(n0B + r) * DIM + k0 + cc * 8;
            cpa16(d, src);
        }
    };

    float acc[4][4][4];
#pragma unroll
    for (int mt = 0; mt < 4; mt++)
#pragma unroll
        for (int nt = 0; nt < 4; nt++)
#pragma unroll
            for (int q = 0; q < 4; q++) acc[mt][nt][q] = 0.f;

    const int aoff = (m0W + (lane & 15)) * PROWB + (lane >> 4) * 16;
    const int boff = (n0W + (grp >> 1) * 8 + (lane & 7)) * PROWB + (grp & 1) * 16;

    load_stage(0, 0);  CP_COMMIT();
    load_stage(1, 64); CP_COMMIT();

    for (int it = 0; it < 16; it++) {
        CP_WAIT1();
        __syncthreads();
        const uint32_t bo = sb + (it & 1) * QK_STGB;
        const uint32_t aH = bo + 0 * PMATB + aoff;
        const uint32_t bH = bo + 1 * PMATB + boff;

#pragma unroll
        for (int ks = 0; ks < 4; ks++) {
            const int kb = ks * 32;
            uint32_t ah[4][4], bh[4][2];
#pragma unroll
            for (int mt = 0; mt < 4; mt++)
                ldsm4(ah[mt], aH + mt * 16 * PROWB + kb);
#pragma unroll
            for (int bt = 0; bt < 2; bt++) {
                uint32_t t[4];
                ldsm4(t, bH + bt * 16 * PROWB + kb);
                bh[bt * 2][0] = t[0]; bh[bt * 2][1] = t[1];
                bh[bt * 2 + 1][0] = t[2]; bh[bt * 2 + 1][1] = t[3];
            }
#pragma unroll
            for (int mt = 0; mt < 4; mt++)
#pragma unroll
                for (int nt = 0; nt < 4; nt++)
                    mma16816(acc[mt][nt], ah[mt], bh[nt]);
        }
        __syncthreads();
        const int ns = (it + 2 < 16) ? (it + 2) : 15;
        load_stage((it + 2) & 1, ns * 64);
        CP_COMMIT();
    }

    const int rr  = lane >> 2;
    const int cc2 = (lane & 3) * 2;
#pragma unroll
    for (int mt = 0; mt < 4; mt++) {
#pragma unroll
        for (int hp = 0; hp < 2; hp++) {
            const int m = m0B + m0W + mt * 16 + rr + hp * 8;
            const int n = m >> 11;
            const int l = m & 2047;
            const float ksc = (which == 1) ? g_rscale[n] * 1.44269504f : 1.0f;
            const size_t rowb = ((size_t)(n * NH) * LQ + l) * DH;
#pragma unroll
            for (int nt = 0; nt < 4; nt++) {
                const int j  = n0B + n0W + nt * 8 + cc2;
                const int h  = j >> 6;
                const int dh = j & 63;
                *reinterpret_cast<uint32_t*>(&OutH[rowb + (size_t)h * LQ * DH + dh]) =
                    h2_only(acc[mt][nt][hp * 2 + 0] * ksc,
                            acc[mt][nt][hp * 2 + 1] * ksc);
            }
        }
    }
}

// ============ V projection: 2-pass, 3 mats/stage, occ 2, BK=64 ===============
#define V_STGB  (3 * PMATB)              // 55296 per stage (Ah, Al, Bh)
#define V_SMEM  (2 * V_STGB)             // 110592

__global__ __launch_bounds__(256, 2)
void v_proj_kernel(int dummy) {
    extern __shared__ char smem[];
    const uint32_t sb = smem_u32(smem);

    const int tid  = threadIdx.x;
    const int wid  = tid >> 5;
    const int lane = tid & 31;
    const int grp  = lane >> 3;

    const __half* __restrict__ XH = g_Xkh;
    const __half* __restrict__ XL = g_Xkl;
    const __half* __restrict__ WH = g_Wh + 2 * (size_t)DIM * DIM;

    const int m0B = blockIdx.y * 128;
    const int n0B = blockIdx.x * 128;
    const int m0W = (wid >> 2) * 64;
    const int n0W = (wid & 3) * 32;

    // stage: 3 mats x 128 rows x 8 chunks = 3072 chunks -> 12 per thread
    auto load_stage = [&](int buf, int k0) {
        const uint32_t bo = sb + buf * V_STGB;
#pragma unroll
        for (int i = 0; i < 12; i++) {
            int slot = tid + i * 256;
            int mat = slot >> 10;            // 0:Ah 1:Al 2:Bh
            int r   = (slot >> 3) & 127;
            int cc  = slot & 7;
            uint32_t d = bo + mat * PMATB + r * PROWB + cc * 16;
            const __half* src =
                (mat == 0) ? XH + (size_t)(m0B + r) * DIM + k0 + cc * 8 :
                (mat == 1) ? XL + (size_t)(m0B + r) * DIM + k0 + cc * 8 :
                             WH + (size_t)(n0B + r) * DIM + k0 + cc * 8;
            cpa16(d, src);
        }
    };

    float acc[4][4][4];
#pragma unroll
    for (int mt = 0; mt < 4; mt++)
#pragma unroll
        for (int nt = 0; nt < 4; nt++)
#pragma unroll
            for (int q = 0; q < 4; q++) acc[mt][nt][q] = 0.f;

    const int aoff = (m0W + (lane & 15)) * PROWB + (lane >> 4) * 16;
    const int boff = (n0W + (grp >> 1) * 8 + (lane & 7)) * PROWB + (grp & 1) * 16;

    load_stage(0, 0);  CP_COMMIT();
    load_stage(1, 64); CP_COMMIT();

    for (int it = 0; it < 16; it++) {
        CP_WAIT1();
        __syncthreads();
        const uint32_t bo = sb + (it & 1) * V_STGB;
        const uint32_t aH = bo + 0 * PMATB + aoff;
        const uint32_t aL = bo + 1 * PMATB + aoff;
        const uint32_t bH = bo + 2 * PMATB + boff;

#pragma unroll
        for (int ks = 0; ks < 4; ks++) {
            const int kb = ks * 32;
            uint32_t ah[4][4], al[4][4], bh[4][2];
#pragma unroll
            for (int mt = 0; mt < 4; mt++) {
                ldsm4(ah[mt], aH + mt * 16 * PROWB + kb);
                ldsm4(al[mt], aL + mt * 16 * PROWB + kb);
            }
#pragma unroll
            for (int bt = 0; bt < 2; bt++) {
                uint32_t t[4];
                ldsm4(t, bH + bt * 16 * PROWB + kb);
                bh[bt * 2][0] = t[0]; bh[bt * 2][1] = t[1];
                bh[bt * 2 + 1][0] = t[2]; bh[bt * 2 + 1][1] = t[3];
            }
#pragma unroll
            for (int mt = 0; mt < 4; mt++)
#pragma unroll
                for (int nt = 0; nt < 4; nt++) {
                    mma16816(acc[mt][nt], ah[mt], bh[nt]);
                    mma16816(acc[mt][nt], al[mt], bh[nt]);
                }
        }
        __syncthreads();
        const int ns = (it + 2 < 16) ? (it + 2) : 15;
        load_stage((it + 2) & 1, ns * 64);
        CP_COMMIT();
    }

    const int rr  = lane >> 2;
    const int cc2 = (lane & 3) * 2;
#pragma unroll
    for (int mt = 0; mt < 4; mt++) {
#pragma unroll
        for (int hp = 0; hp < 2; hp++) {
            const int m = m0B + m0W + mt * 16 + rr + hp * 8;
            const int n = m >> 11;
            const int l = m & 2047;
            const size_t rowb = ((size_t)(n * NH) * LQ + l) * DH;
#pragma unroll
            for (int nt = 0; nt < 4; nt++) {
                const int j  = n0B + n0W + nt * 8 + cc2;
                const int h  = j >> 6;
                const int dh = j & 63;
                *reinterpret_cast<uint32_t*>(&g_Vh[rowb + (size_t)h * LQ * DH + dh]) =
                    h2_only(acc[mt][nt][hp * 2 + 0], acc[mt][nt][hp * 2 + 1]);
            }
        }
    }
}

// ================= FA2 attention, fp16 HMMA (unchanged from R15) ============
#define ASTR    72
#define AROWB   (ASTR * 2)               // 144 bytes
#define AQB     (128 * AROWB)            // 18432 (Qh only)
#define AKB     (64 * AROWB)             // 9216 per K/V matrix
#define ASTG0   AQB                      // 18432
#define ASTGB   (2 * AKB)                // 18432 per stage (Kh,Vh)
#define ASMEM   (ASTG0 + 2 * ASTGB)      // 55296

__global__ __launch_bounds__(256, 2)
void attn_mma_kernel(float* __restrict__ out) {
    extern __shared__ char smem[];
    const uint32_t sb = smem_u32(smem);

    const int tid  = threadIdx.x;
    const int wid  = tid >> 5;
    const int lane = tid & 31;
    const int grp  = lane >> 3;

    const int q0 = (gridDim.x - 1 - blockIdx.x) * 128;
    const int nh = blockIdx.y;
    const int n  = nh >> 4;
    const int h  = nh & 15;

    const int valid = g_valid[n];
    const int kend  = min(valid, q0 + 128);
    const int nkb   = (kend + 63) >> 6;

    const size_t base = (size_t)nh * LK * DH;
    const __half* __restrict__ Qhb = g_Qh + base;
    const __half* __restrict__ Khb = g_Kh + base;
    const __half* __restrict__ Vhb = g_Vh + base;

    auto load_q = [&]() {
#pragma unroll
        for (int i = 0; i < 4; i++) {
            int c  = tid + i * 256;
            int r  = c >> 3;
            int cc = c & 7;
            cpa16(sb + r * AROWB + cc * 16, Qhb + (size_t)(q0 + r) * DH + cc * 8);
        }
    };
    auto load_kv = [&](int buf, int kb) {
        const int k0 = kb * 64;
        const uint32_t so = sb + ASTG0 + buf * ASTGB;
#pragma unroll
        for (int i = 0; i < 4; i++) {
            int c   = tid + i * 256;
            int mat = c >> 9;
            int r   = (c >> 3) & 63;
            int cc  = c & 7;
            const __half* src = (mat == 0) ? Khb : Vhb;
            src += (size_t)(k0 + r) * DH + cc * 8;
            cpa16(so + mat * AKB + r * AROWB + cc * 16, src);
        }
    };

    const int wq0 = wid * 16;
    const int r0  = lane >> 2;
    const int qr0 = q0 + wq0 + r0;
    const int qr1 = qr0 + 8;

    const int qoff = (wq0 + (lane & 15)) * AROWB + (lane >> 4) * 16;
    const int koff = ((grp >> 1) * 8 + (lane & 7)) * AROWB + (grp & 1) * 16;
    const int voff = ((grp & 1) * 8 + (lane & 7)) * AROWB + (grp >> 1) * 16;

    uint32_t qh[4][4];
    float o[8][4];
#pragma unroll
    for (int nt = 0; nt < 8; nt++)
#pragma unroll
        for (int q = 0; q < 4; q++) o[nt][q] = 0.f;
    float m0 = -1e30f, m1 = -1e30f, l0 = 0.f, l1 = 0.f;

    load_q();
    load_kv(0, 0);
    CP_COMMIT();
    load_kv(1, (nkb > 1) ? 1 : 0);
    CP_COMMIT();

    for (int kb = 0; kb < nkb; kb++) {
        CP_WAIT1();
        __syncthreads();
        const int k0 = kb * 64;
        const uint32_t so = sb + ASTG0 + (kb & 1) * ASTGB;

        if (kb == 0) {
#pragma unroll
            for (int kt = 0; kt < 4; kt++)
                ldsm4(qh[kt], sb + qoff + kt * 32);
        }

        float sc[8][4];
#pragma unroll
        for (int nt = 0; nt < 8; nt++)
#pragma unroll
            for (int q = 0; q < 4; q++) sc[nt][q] = 0.f;

#pragma unroll
        for (int kt = 0; kt < 4; kt++) {
            uint32_t bh[8][2];
#pragma unroll
            for (int bt = 0; bt < 4; bt++) {
                uint32_t t[4];
                ldsm4(t, so + 0 * AKB + koff + bt * 16 * AROWB + kt * 32);
                bh[bt * 2][0] = t[0]; bh[bt * 2][1] = t[1];
                bh[bt * 2 + 1][0] = t[2]; bh[bt * 2 + 1][1] = t[3];
            }
#pragma unroll
            for (int nt = 0; nt < 8; nt++)
                mma16816(sc[nt], qh[kt], bh[nt]);
        }

        if (k0 + 63 > q0 + wq0 || k0 + 64 > valid) {
#pragma unroll
            for (int nt = 0; nt < 8; nt++) {
                const int kc = k0 + nt * 8 + (lane & 3) * 2;
                if (kc     > qr0 || kc     >= valid) sc[nt][0] = -1e30f;
                if (kc + 1 > qr0 || kc + 1 >= valid) sc[nt][1] = -1e30f;
                if (kc     > qr1 || kc     >= valid) sc[nt][2] = -1e30f;
                if (kc + 1 > qr1 || kc + 1 >= valid) sc[nt][3] = -1e30f;
            }
        }

        float mx0 = -1e30f, mx1 = -1e30f;
#pragma unroll
        for (int nt = 0; nt < 8; nt++) {
            mx0 = fmaxf(mx0, fmaxf(sc[nt][0], sc[nt][1]));
            mx1 = fmaxf(mx1, fmaxf(sc[nt][2], sc[nt][3]));
        }
        mx0 = fmaxf(mx0, __shfl_xor_sync(0xffffffffu, mx0, 1));
        mx0 = fmaxf(mx0, __shfl_xor_sync(0xffffffffu, mx0, 2));
        mx1 = fmaxf(mx1, __shfl_xor_sync(0xffffffffu, mx1, 1));
        mx1 = fmaxf(mx1, __shfl_xor_sync(0xffffffffu, mx1, 2));
        const float mn0 = fmaxf(m0, mx0);
        const float mn1 = fmaxf(m1, mx1);
        const float f0 = ex2(m0 - mn0);
        const float f1 = ex2(m1 - mn1);
        m0 = mn0; m1 = mn1;

        float s0 = 0.f, s1 = 0.f;
#pragma unroll
        for (int nt = 0; nt < 8; nt++) {
            sc[nt][0] = ex2(sc[nt][0] - mn0);
            sc[nt][1] = ex2(sc[nt][1] - mn0);
            sc[nt][2] = ex2(sc[nt][2] - mn1);
            sc[nt][3] = ex2(sc[nt][3] - mn1);
            s0 += sc[nt][0] + sc[nt][1];
            s1 += sc[nt][2] + sc[nt][3];
        }
        s0 += __shfl_xor_sync(0xffffffffu, s0, 1);
        s0 += __shfl_xor_sync(0xffffffffu, s0, 2);
        s1 += __shfl_xor_sync(0xffffffffu, s1, 1);
        s1 += __shfl_xor_sync(0xffffffffu, s1, 2);
        l0 = l0 * f0 + s0;
        l1 = l1 * f1 + s1;

#pragma unroll
        for (int nt = 0; nt < 8; nt++) {
            o[nt][0] *= f0; o[nt][1] *= f0;
            o[nt][2] *= f1; o[nt][3] *= f1;
        }

#pragma unroll
        for (int kt = 0; kt < 4; kt++) {
            uint32_t ah[4];
            ah[0] = h2_only(sc[2 * kt][0],     sc[2 * kt][1]);
            ah[1] = h2_only(sc[2 * kt][2],     sc[2 * kt][3]);
            ah[2] = h2_only(sc[2 * kt + 1][0], sc[2 * kt + 1][1]);
            ah[3] = h2_only(sc[2 * kt + 1][2], sc[2 * kt + 1][3]);

            uint32_t bvh[8][2];
#pragma unroll
            for (int jp = 0; jp < 4; jp++) {
                uint32_t t[4];
                ldsm4t(t, so + 1 * AKB + voff + kt * 16 * AROWB + jp * 32);
                bvh[jp * 2][0] = t[0]; bvh[jp * 2][1] = t[1];
                bvh[jp * 2 + 1][0] = t[2]; bvh[jp * 2 + 1][1] = t[3];
            }
#pragma unroll
            for (int nt = 0; nt < 8; nt++)
                mma16816(o[nt], ah, bvh[nt]);
        }

        __syncthreads();
        const int nb2 = (kb + 2 < nkb) ? (kb + 2) : (nkb - 1);
        load_kv((kb + 2) & 1, nb2);
        CP_COMMIT();
    }

    const float il0 = 1.0f / l0;
    const float il1 = 1.0f / l1;
    const int lr0 = q0 + wq0 + r0;
    float* orow0 = &out[((size_t)n * LQ + lr0) * DIM + h * DH];
    float* orow1 = &out[((size_t)n * LQ + lr0 + 8) * DIM + h * DH];
#pragma unroll
    for (int nt = 0; nt < 8; nt++) {
        const int dh = nt * 8 + (lane & 3) * 2;
        float2 v0; v0.x = o[nt][0] * il0; v0.y = o[nt][1] * il0;
        float2 v1; v1.x = o[nt][2] * il1; v1.y = o[nt][3] * il1;
        *reinterpret_cast<float2*>(orow0 + dh) = v0;
        *reinterpret_cast<float2*>(orow1 + dh) = v1;
    }
}

// ----------------------------- launcher -------------------------------------
extern "C" void kernel_launch(void* const* d_in, const int* in_sizes, int n_in,
                              void* d_out, int out_size) {
    const float* query = (const float*)d_in[0];
    const float* key   = (const float*)d_in[1];
    const float* Wq    = (const float*)d_in[2];
    const float* Wk    = (const float*)d_in[3];
    const float* Wv    = (const float*)d_in[4];
    const void* pad = (in_sizes[6] == NB * LK) ? d_in[6]
                    : (in_sizes[5] == NB * LK) ? d_in[5]
                    : d_in[6];
    float* out = (float*)d_out;

    prep_kernel<<<PREP_BLOCKS, 256>>>(query, key, Wq, Wk, Wv, pad);

    cudaFuncSetAttribute(qk_proj_kernel,
                         cudaFuncAttributeMaxDynamicSharedMemorySize, QK_SMEM);
    dim3 qkgrid(DIM / 128, (NB * LQ) / 128, 2);   // (8, 64, 2)
    qk_proj_kernel<<<qkgrid, 256, QK_SMEM>>>(0);

    cudaFuncSetAttribute(v_proj_kernel,
                         cudaFuncAttributeMaxDynamicSharedMemorySize, V_SMEM);
    dim3 vgrid(DIM / 128, (NB * LQ) / 128);       // (8, 64)
    v_proj_kernel<<<vgrid, 256, V_SMEM>>>(0);

    cudaFuncSetAttribute(attn_mma_kernel,
                         cudaFuncAttributeMaxDynamicSharedMemorySize, ASMEM);
    dim3 agrid(LQ / 128, NB * NH);
    attn_mma_kernel<<<agrid, 256, ASMEM>>>(out);
}